// round 2
// baseline (speedup 1.0000x reference)
#include <cuda_runtime.h>
#include <cuda_bf16.h>
#include <math.h>

#define INF_F 1e10f

// ---------------- scratch (device globals; no allocations allowed) -------------
// normalized rows: [3 inputs][8 batch * 1024 rows][64]
__device__ float g_norm[3u * 8192u * 64u];
// cost matrices, anti-diagonal-major: [32 problems][2047 diagonals][1024 i-positions]
__device__ float g_cost[32ull * 2047ull * 1024ull];
// DTW results: [pair 0..3][batch 0..7]
__device__ float g_R[32];

// ---------------- kernel 1: row-wise L2 normalize ------------------------------
__global__ void norm_kernel(const float* __restrict__ A,
                            const float* __restrict__ B,
                            const float* __restrict__ C) {
    const int sel  = blockIdx.y;                  // 0..2
    const int lane = threadIdx.x & 31;
    const int row  = blockIdx.x * 8 + (threadIdx.x >> 5);   // 0..8191
    const float* src = (sel == 0) ? A : ((sel == 1) ? B : C);

    float2 v = *(const float2*)(src + (size_t)row * 64 + lane * 2);
    float ss = v.x * v.x + v.y * v.y;
    #pragma unroll
    for (int o = 16; o > 0; o >>= 1) ss += __shfl_xor_sync(0xffffffffu, ss, o);
    float nrm   = sqrtf(ss);
    float scale = 1.0f / fmaxf(nrm, 1e-8f);
    float* dst = g_norm + (size_t)sel * (8192u * 64u) + (size_t)row * 64 + lane * 2;
    *(float2*)dst = make_float2(v.x * scale, v.y * scale);
}

// ---------------- kernel 2: cost = 1 - dot, written diagonal-major -------------
// grid: (16 i-tiles, 16 j-tiles, 32 problems), 64 threads, 8x8 microtile
__global__ void __launch_bounds__(64) cost_kernel() {
    const int pb  = blockIdx.z;            // problem: p*8 + batch
    const int p   = pb >> 3;
    const int bat = pb & 7;
    const int asel = p >> 1;               // p0,p1 -> TGT(0); p2,p3 -> OTH(1)
    const int bsel = (p & 1) ? asel : 2;   // odd p -> self; even p -> X(2)

    const float* Abase = g_norm + ((size_t)asel * 8192u + (size_t)bat * 1024u) * 64u;
    const float* Bbase = g_norm + ((size_t)bsel * 8192u + (size_t)bat * 1024u) * 64u;
    const int i0 = blockIdx.x * 64;
    const int j0 = blockIdx.y * 64;

    __shared__ float sAT[64 * 64];   // transposed: sAT[k*64 + i]
    __shared__ float sBT[64 * 64];   // transposed: sBT[k*64 + j]

    const int tid = threadIdx.x;     // 0..63

    // each thread loads one full A row and one full B row, stores transposed
    {
        const float4* ap = (const float4*)(Abase + (size_t)(i0 + tid) * 64);
        const float4* bp = (const float4*)(Bbase + (size_t)(j0 + tid) * 64);
        #pragma unroll
        for (int q = 0; q < 16; q++) {
            float4 va = ap[q];
            sAT[(4 * q + 0) * 64 + tid] = va.x;
            sAT[(4 * q + 1) * 64 + tid] = va.y;
            sAT[(4 * q + 2) * 64 + tid] = va.z;
            sAT[(4 * q + 3) * 64 + tid] = va.w;
            float4 vb = bp[q];
            sBT[(4 * q + 0) * 64 + tid] = vb.x;
            sBT[(4 * q + 1) * 64 + tid] = vb.y;
            sBT[(4 * q + 2) * 64 + tid] = vb.z;
            sBT[(4 * q + 3) * 64 + tid] = vb.w;
        }
    }
    __syncthreads();

    const int ti = tid >> 3;   // 0..7  (i direction, x8)
    const int tj = tid & 7;    // 0..7  (j direction, x8)

    float acc[8][8];
    #pragma unroll
    for (int r = 0; r < 8; r++)
        #pragma unroll
        for (int c = 0; c < 8; c++) acc[r][c] = 0.0f;

    #pragma unroll
    for (int k = 0; k < 64; k++) {
        float a[8], b[8];
        float4 t0 = *(const float4*)&sAT[k * 64 + ti * 8];
        float4 t1 = *(const float4*)&sAT[k * 64 + ti * 8 + 4];
        a[0] = t0.x; a[1] = t0.y; a[2] = t0.z; a[3] = t0.w;
        a[4] = t1.x; a[5] = t1.y; a[6] = t1.z; a[7] = t1.w;
        float4 u0 = *(const float4*)&sBT[k * 64 + tj * 8];
        float4 u1 = *(const float4*)&sBT[k * 64 + tj * 8 + 4];
        b[0] = u0.x; b[1] = u0.y; b[2] = u0.z; b[3] = u0.w;
        b[4] = u1.x; b[5] = u1.y; b[6] = u1.z; b[7] = u1.w;
        #pragma unroll
        for (int r = 0; r < 8; r++)
            #pragma unroll
            for (int c = 0; c < 8; c++)
                acc[r][c] = fmaf(a[r], b[c], acc[r][c]);
    }
    __syncthreads();

    // restage tile into shared (alias over sAT) for coalesced diagonal writes
    float* Cs = sAT;
    #pragma unroll
    for (int r = 0; r < 8; r++) {
        *(float4*)&Cs[(ti * 8 + r) * 64 + tj * 8]     =
            make_float4(acc[r][0], acc[r][1], acc[r][2], acc[r][3]);
        *(float4*)&Cs[(ti * 8 + r) * 64 + tj * 8 + 4] =
            make_float4(acc[r][4], acc[r][5], acc[r][6], acc[r][7]);
    }
    __syncthreads();

    float* out = g_cost + (size_t)pb * (2047ull * 1024ull);
    const int kbase = i0 + j0;
    for (int d = 0; d < 127; d++) {
        int lo = d - 63; if (lo < 0) lo = 0;
        int hi = d;      if (hi > 63) hi = 63;
        int i = lo + tid;
        if (i <= hi) {
            out[(size_t)(kbase + d) * 1024u + (i0 + i)] = 1.0f - Cs[i * 64 + (d - i)];
        }
    }
}

// ---------------- kernel 3: soft-DTW DP over anti-diagonals --------------------
// one CTA (1024 threads) per problem; thread t owns matrix row i = t.
__global__ void __launch_bounds__(1024) dp_kernel() {
    const int prob = blockIdx.x;
    const float* __restrict__ D = g_cost + (size_t)prob * (2047ull * 1024ull);
    const int t    = threadIdx.x;
    const int lane = t & 31;
    const int wrp  = t >> 5;

    __shared__ float edge[3][32];   // edge[k%3][warp] = cur at i = warp*32+31
    if (t < 96) (&edge[0][0])[t] = INF_F;
    __syncthreads();

    float r1 = INF_F;   // R_{k-1}[t]
    float r2 = INF_F;   // R_{k-2}[t]
    float d0 = (t == 0) ? D[0] : 0.0f;   // prefetched cost for diag k at row t
    int k = 0;

#define DTW_STEP(SA, SB, SW)                                                     \
    {                                                                            \
        float a = __shfl_up_sync(0xffffffffu, r2, 1);                            \
        float b = __shfl_up_sync(0xffffffffu, r1, 1);                            \
        if (lane == 0) {                                                         \
            if (wrp == 0) { a = (k == 0) ? 0.0f : INF_F; b = INF_F; }            \
            else          { a = edge[SA][wrp - 1]; b = edge[SB][wrp - 1]; }      \
        }                                                                        \
        float m   = fminf(fminf(a, b), r1);                                      \
        float s   = __expf(m - a) + __expf(m - b) + __expf(m - r1);              \
        float cur = ((unsigned)(k - t) < 1024u) ? (d0 + m - __logf(s)) : INF_F;  \
        d0 = 0.0f;                                                               \
        int kn = k + 1;                                                          \
        if ((unsigned)(kn - t) < 1024u) d0 = D[(size_t)kn * 1024u + t];          \
        if (lane == 31) edge[SW][wrp] = cur;                                     \
        r2 = r1; r1 = cur;                                                       \
        __syncthreads();                                                         \
        k++;                                                                     \
    }

    // 2047 steps = 682*3 + 1; slot indices: write k%3, read b=(k-1)%3, a=(k-2)%3
    for (int it = 0; it < 682; ++it) {
        DTW_STEP(1, 2, 0)   // k%3 == 0
        DTW_STEP(2, 0, 1)   // k%3 == 1
        DTW_STEP(0, 1, 2)   // k%3 == 2
    }
    DTW_STEP(1, 2, 0)       // k = 2046 (2046%3 == 0)
#undef DTW_STEP

    if (t == 1023) g_R[prob] = r1;   // R[1023][1023]
}

// ---------------- kernel 4: combine into the MSE loss --------------------------
__global__ void combine_kernel(const float* __restrict__ labels, float* __restrict__ out) {
    const int b = threadIdx.x;   // 0..31, only 0..7 active
    float v = 0.0f;
    if (b < 8) {
        float sTX = g_R[0 * 8 + b];
        float sTT = g_R[1 * 8 + b];
        float sOX = g_R[2 * 8 + b];
        float sOO = g_R[3 * 8 + b];
        // sdtw(X,X) cancels exactly in d_tgt - d_oth
        float diff = (sTX - sOX) - 0.5f * (sTT - sOO) - labels[0];
        v = diff * diff;
    }
    #pragma unroll
    for (int o = 4; o > 0; o >>= 1) v += __shfl_down_sync(0xffffffffu, v, o);
    if (b == 0) out[0] = v * 0.125f;
}

// ---------------- launcher -----------------------------------------------------
extern "C" void kernel_launch(void* const* d_in, const int* in_sizes, int n_in,
                              void* d_out, int out_size) {
    const float* TGT    = (const float*)d_in[0];
    const float* OTH    = (const float*)d_in[1];
    const float* X      = (const float*)d_in[2];
    const float* labels = (const float*)d_in[3];
    float* out = (float*)d_out;

    norm_kernel<<<dim3(1024, 3), 256>>>(TGT, OTH, X);
    cost_kernel<<<dim3(16, 16, 32), 64>>>();
    dp_kernel<<<32, 1024>>>();
    combine_kernel<<<1, 32>>>(labels, out);
}